// round 15
// baseline (speedup 1.0000x reference)
#include <cuda_runtime.h>

#define BATCH 4
#define SEQ   2048
#define HID   1024
#define NHEAD 16
#define HDIM  64

// Scratch (static device globals — allowed; no runtime allocation)
__device__ float g_q[BATCH*NHEAD*SEQ*HDIM];
__device__ float g_k[BATCH*NHEAD*SEQ*HDIM];
__device__ float g_v[BATCH*NHEAD*SEQ*HDIM];
__device__ float g_attn[BATCH*SEQ*HID];

// ---------------------------------------------------------------------------
// Stage 1: QKV GEMM, BK=16, DOUBLE-BUFFERED smem (one __syncthreads per
// k-iteration). Same tiles / arithmetic order as R13; epilogue unchanged.
// ---------------------------------------------------------------------------
__global__ __launch_bounds__(256) void qkv_gemm(const float* __restrict__ A,
                                                const float* __restrict__ W,
                                                const float* __restrict__ bias)
{
    const int K = HID;
    const int N = 3 * HID;
    __shared__ float As[2][16][128];
    __shared__ float Bs[2][16][128];

    const int tid = threadIdx.x;
    const int m0 = blockIdx.y * 128;
    const int n0 = blockIdx.x * 128;

    const int arow  = tid >> 1;          // 0..127
    const int acolb = (tid & 1) * 8;     // 0 or 8
    const int brow  = tid >> 5;          // 0..7 (also handles brow+8)
    const int bcol  = (tid & 31) * 4;    // 0..124

    const float* Ap = A + (m0 + arow) * K + acolb;
    const float* Bp = W + brow * N + n0 + bcol;

    float acc[8][8] = {};
    const int ty = tid >> 4, tx = tid & 15;

    // stage tile 0 and store into buffer 0
    float4 av0 = *(const float4*)(Ap);
    float4 av1 = *(const float4*)(Ap + 4);
    float4 bv0 = *(const float4*)(Bp);
    float4 bv1 = *(const float4*)(Bp + (long)8 * N);
    As[0][acolb + 0][arow] = av0.x;
    As[0][acolb + 1][arow] = av0.y;
    As[0][acolb + 2][arow] = av0.z;
    As[0][acolb + 3][arow] = av0.w;
    As[0][acolb + 4][arow] = av1.x;
    As[0][acolb + 5][arow] = av1.y;
    As[0][acolb + 6][arow] = av1.z;
    As[0][acolb + 7][arow] = av1.w;
    *(float4*)&Bs[0][brow    ][bcol] = bv0;
    *(float4*)&Bs[0][brow + 8][bcol] = bv1;

    int buf = 0;
    for (int k0 = 0; k0 < K; k0 += 16) {
        __syncthreads();   // STS for 'buf' visible; reads of buf^1 (iter-1) done
        const bool more = (k0 + 16 < K);
        if (more) {        // prefetch next tile; latency overlaps compute below
            av0 = *(const float4*)(Ap + k0 + 16);
            av1 = *(const float4*)(Ap + k0 + 20);
            bv0 = *(const float4*)(Bp + (long)(k0 + 16) * N);
            bv1 = *(const float4*)(Bp + (long)(k0 + 24) * N);
        }

        #pragma unroll
        for (int kk = 0; kk < 16; kk++) {
            float4 a0 = *(const float4*)&As[buf][kk][ty * 8];
            float4 a1 = *(const float4*)&As[buf][kk][ty * 8 + 4];
            float4 b0 = *(const float4*)&Bs[buf][kk][tx * 8];
            float4 b1 = *(const float4*)&Bs[buf][kk][tx * 8 + 4];
            float a[8] = {a0.x,a0.y,a0.z,a0.w,a1.x,a1.y,a1.z,a1.w};
            float b[8] = {b0.x,b0.y,b0.z,b0.w,b1.x,b1.y,b1.z,b1.w};
            #pragma unroll
            for (int i = 0; i < 8; i++)
                #pragma unroll
                for (int j = 0; j < 8; j++)
                    acc[i][j] += a[i] * b[j];
        }

        if (more) {        // stage into the other buffer
            const int nb = buf ^ 1;
            As[nb][acolb + 0][arow] = av0.x;
            As[nb][acolb + 1][arow] = av0.y;
            As[nb][acolb + 2][arow] = av0.z;
            As[nb][acolb + 3][arow] = av0.w;
            As[nb][acolb + 4][arow] = av1.x;
            As[nb][acolb + 5][arow] = av1.y;
            As[nb][acolb + 6][arow] = av1.z;
            As[nb][acolb + 7][arow] = av1.w;
            *(float4*)&Bs[nb][brow    ][bcol] = bv0;
            *(float4*)&Bs[nb][brow + 8][bcol] = bv1;
            buf = nb;
        }
    }

    #pragma unroll
    for (int i = 0; i < 8; i++) {
        const int m = m0 + ty * 8 + i;
        const int bb = m >> 11;          // / SEQ
        const int s  = m & 2047;
        #pragma unroll
        for (int j = 0; j < 8; j++) {
            const int n = n0 + tx * 8 + j;
            const float v = acc[i][j] + bias[n];
            const int which = n >> 10;
            const int rem = n & 1023;
            const int h = rem >> 6;
            const int d = rem & 63;
            const int idx = (((bb * NHEAD) + h) * SEQ + s) * HDIM + d;
            if (which == 0)      g_q[idx] = v;
            else if (which == 1) g_k[idx] = v;
            else                 g_v[idx] = v;
        }
    }
}

// ---------------------------------------------------------------------------
// Stage 2: causal flash attention — byte-identical to the R14 passing version
// (128-query tiles, 8x4 per-thread, fused S-phase).
// smem: 64*132 + 2*64*68 + 128*68 floats = 103424 B.
// ---------------------------------------------------------------------------
__global__ __launch_bounds__(256, 2) void flash_attn()
{
    extern __shared__ float sm[];
    float (*QsT)[132] = (float(*)[132])sm;                          // [d][query]
    float (*KsT)[68]  = (float(*)[68])(sm + 64 * 132);              // [d][key]
    float (*Vs)[68]   = (float(*)[68])(sm + 64 * 132 + 64 * 68);    // [key][d]
    float (*Ps)[68]   = (float(*)[68])(sm + 64 * 132 + 2 * 64 * 68);// [query][key]

    const int b  = blockIdx.z;
    const int h  = blockIdx.y;
    const int qt = blockIdx.x;
    const int q0 = qt * 128;

    const float* Qg  = g_q + (((long)(b * NHEAD + h)) * SEQ + q0) * HDIM;
    const float* Kg0 = g_k + ((long)(b * NHEAD + h)) * SEQ * HDIM;
    const float* Vg0 = g_v + ((long)(b * NHEAD + h)) * SEQ * HDIM;

    const int tid = threadIdx.x;
    const int ty = tid >> 4, tx = tid & 15;
    const int rbase = 8 * ty;

    // load Q tile transposed: QsT[d][q] = Q[q][d]  (128 rows x 64 d)
    for (int i = tid; i < 128 * 64; i += 256) {
        const int r = i >> 6, c = i & 63;
        QsT[c][r] = Qg[i];
    }

    float m_i[8], l_i[8], acc[8][4];
    #pragma unroll
    for (int i = 0; i < 8; i++) {
        m_i[i] = -1e30f;
        l_i[i] = 0.0f;
        #pragma unroll
        for (int j = 0; j < 4; j++) acc[i][j] = 0.0f;
    }

    const float scale = 0.125f; // HD^-0.5
    const int ntiles = 2 * qt + 2;

    for (int t = 0; t < ntiles; t++) {
        const int k0 = t * 64;
        __syncthreads();   // prior tile's K/V reads done (and Q load at t=0)
        for (int i = tid; i < 64 * 64; i += 256) {
            const int r = i >> 6, c = i & 63;
            KsT[c][r] = Kg0[k0 * HDIM + i];   // [d][key]
            Vs[r][c]  = Vg0[k0 * HDIM + i];   // [key][d]
        }
        __syncthreads();

        // S = Q K^T fused over all 8 rows: per d, 2 q-float4 + 1 k-float4
        float s[8][4];
        #pragma unroll
        for (int i = 0; i < 8; i++)
            #pragma unroll
            for (int j = 0; j < 4; j++) s[i][j] = 0.0f;

        #pragma unroll 4
        for (int d = 0; d < 64; d++) {
            const float4 qa = *(const float4*)&QsT[d][rbase];
            const float4 qb = *(const float4*)&QsT[d][rbase + 4];
            const float4 k4 = *(const float4*)&KsT[d][4 * tx];
            const float qv[8] = {qa.x, qa.y, qa.z, qa.w, qb.x, qb.y, qb.z, qb.w};
            const float kv[4] = {k4.x, k4.y, k4.z, k4.w};
            #pragma unroll
            for (int i = 0; i < 8; i++)
                #pragma unroll
                for (int j = 0; j < 4; j++)
                    s[i][j] += qv[i] * kv[j];
        }

        // mask + softmax + P write, per 4-row half (guards preserved)
        #pragma unroll
        for (int hf = 0; hf < 2; hf++) {
            const int rb = rbase + 4 * hf;
            const bool active = (q0 + rb + 3 >= k0);
            if (active) {
                #pragma unroll
                for (int i = 0; i < 4; i++) {
                    const int ii = 4 * hf + i;
                    const int rg = q0 + rb + i;
                    #pragma unroll
                    for (int j = 0; j < 4; j++) {
                        const int cg = k0 + 4 * tx + j;
                        float val = s[ii][j] * scale;
                        if (cg > rg) val = -1e30f;
                        s[ii][j] = val;
                    }
                }
                #pragma unroll
                for (int i = 0; i < 4; i++) {
                    const int ii = 4 * hf + i;
                    float mx = fmaxf(fmaxf(s[ii][0], s[ii][1]),
                                     fmaxf(s[ii][2], s[ii][3]));
                    #pragma unroll
                    for (int off = 8; off >= 1; off >>= 1)
                        mx = fmaxf(mx, __shfl_xor_sync(0xffffffffu, mx, off));
                    const float mn = fmaxf(m_i[ii], mx);
                    const float corr = __expf(m_i[ii] - mn);
                    m_i[ii] = mn;
                    float rs = 0.0f;
                    #pragma unroll
                    for (int j = 0; j < 4; j++) {
                        s[ii][j] = __expf(s[ii][j] - mn);
                        rs += s[ii][j];
                    }
                    #pragma unroll
                    for (int off = 8; off >= 1; off >>= 1)
                        rs += __shfl_xor_sync(0xffffffffu, rs, off);
                    l_i[ii] = l_i[ii] * corr + rs;
                    #pragma unroll
                    for (int j = 0; j < 4; j++) acc[ii][j] *= corr;
                }
                #pragma unroll
                for (int i = 0; i < 4; i++)
                    #pragma unroll
                    for (int j = 0; j < 4; j++)
                        Ps[rb + i][4 * tx + j] = s[4 * hf + i][j];
            } else {
                // fully masked half: P rows are exactly zero
                #pragma unroll
                for (int i = 0; i < 4; i++)
                    #pragma unroll
                    for (int j = 0; j < 4; j++)
                        Ps[rb + i][4 * tx + j] = 0.0f;
            }
        }
        __syncwarp();   // P rows exchanged only within the 16-lane tx group

        // O += P V : kk chunks of 4 (pv and vv both LDS.128)
        #pragma unroll 2
        for (int kk = 0; kk < 64; kk += 4) {
            float4 pv4[8];
            #pragma unroll
            for (int i = 0; i < 8; i++)
                pv4[i] = *(const float4*)&Ps[rbase + i][kk];
            float4 vv[4];
            #pragma unroll
            for (int c = 0; c < 4; c++)
                vv[c] = *(const float4*)&Vs[kk + c][4 * tx];
            #pragma unroll
            for (int i = 0; i < 8; i++) {
                const float pv[4] = {pv4[i].x, pv4[i].y, pv4[i].z, pv4[i].w};
                #pragma unroll
                for (int c = 0; c < 4; c++) {   // kk-sequential: same order as before
                    acc[i][0] += pv[c] * vv[c].x;
                    acc[i][1] += pv[c] * vv[c].y;
                    acc[i][2] += pv[c] * vv[c].z;
                    acc[i][3] += pv[c] * vv[c].w;
                }
            }
        }
        __syncwarp();   // own P rows fully consumed before next overwrite
    }

    // write out: g_attn[b][s][h*HD + d]
    #pragma unroll
    for (int i = 0; i < 8; i++) {
        const int rg = q0 + rbase + i;
        const float inv_l = 1.0f / l_i[i];
        #pragma unroll
        for (int j = 0; j < 4; j++) {
            g_attn[((long)(b * SEQ + rg)) * HID + h * HDIM + 4 * tx + j] =
                acc[i][j] * inv_l;
        }
    }
}

// ---------------------------------------------------------------------------
// Stage 3: output projection, BK=16, DOUBLE-BUFFERED (same as qkv_gemm).
// ---------------------------------------------------------------------------
__global__ __launch_bounds__(256) void out_gemm(const float* __restrict__ W,
                                                const float* __restrict__ bias,
                                                float* __restrict__ Out)
{
    const int K = HID;
    const int N = HID;
    __shared__ float As[2][16][128];
    __shared__ float Bs[2][16][128];

    const int tid = threadIdx.x;
    const int m0 = blockIdx.y * 128;
    const int n0 = blockIdx.x * 128;

    const int arow  = tid >> 1;
    const int acolb = (tid & 1) * 8;
    const int brow  = tid >> 5;
    const int bcol  = (tid & 31) * 4;

    const float* Ap = g_attn + (long)(m0 + arow) * K + acolb;
    const float* Bp = W + brow * N + n0 + bcol;

    float acc[8][8] = {};
    const int ty = tid >> 4, tx = tid & 15;

    float4 av0 = *(const float4*)(Ap);
    float4 av1 = *(const float4*)(Ap + 4);
    float4 bv0 = *(const float4*)(Bp);
    float4 bv1 = *(const float4*)(Bp + (long)8 * N);
    As[0][acolb + 0][arow] = av0.x;
    As[0][acolb + 1][arow] = av0.y;
    As[0][acolb + 2][arow] = av0.z;
    As[0][acolb + 3][arow] = av0.w;
    As[0][acolb + 4][arow] = av1.x;
    As[0][acolb + 5][arow] = av1.y;
    As[0][acolb + 6][arow] = av1.z;
    As[0][acolb + 7][arow] = av1.w;
    *(float4*)&Bs[0][brow    ][bcol] = bv0;
    *(float4*)&Bs[0][brow + 8][bcol] = bv1;

    int buf = 0;
    for (int k0 = 0; k0 < K; k0 += 16) {
        __syncthreads();
        const bool more = (k0 + 16 < K);
        if (more) {
            av0 = *(const float4*)(Ap + k0 + 16);
            av1 = *(const float4*)(Ap + k0 + 20);
            bv0 = *(const float4*)(Bp + (long)(k0 + 16) * N);
            bv1 = *(const float4*)(Bp + (long)(k0 + 24) * N);
        }

        #pragma unroll
        for (int kk = 0; kk < 16; kk++) {
            float4 a0 = *(const float4*)&As[buf][kk][ty * 8];
            float4 a1 = *(const float4*)&As[buf][kk][ty * 8 + 4];
            float4 b0 = *(const float4*)&Bs[buf][kk][tx * 8];
            float4 b1 = *(const float4*)&Bs[buf][kk][tx * 8 + 4];
            float a[8] = {a0.x,a0.y,a0.z,a0.w,a1.x,a1.y,a1.z,a1.w};
            float b[8] = {b0.x,b0.y,b0.z,b0.w,b1.x,b1.y,b1.z,b1.w};
            #pragma unroll
            for (int i = 0; i < 8; i++)
                #pragma unroll
                for (int j = 0; j < 8; j++)
                    acc[i][j] += a[i] * b[j];
        }

        if (more) {
            const int nb = buf ^ 1;
            As[nb][acolb + 0][arow] = av0.x;
            As[nb][acolb + 1][arow] = av0.y;
            As[nb][acolb + 2][arow] = av0.z;
            As[nb][acolb + 3][arow] = av0.w;
            As[nb][acolb + 4][arow] = av1.x;
            As[nb][acolb + 5][arow] = av1.y;
            As[nb][acolb + 6][arow] = av1.z;
            As[nb][acolb + 7][arow] = av1.w;
            *(float4*)&Bs[nb][brow    ][bcol] = bv0;
            *(float4*)&Bs[nb][brow + 8][bcol] = bv1;
            buf = nb;
        }
    }

    #pragma unroll
    for (int i = 0; i < 8; i++) {
        const int m = m0 + ty * 8 + i;
        #pragma unroll
        for (int j = 0; j < 8; j++) {
            const int n = n0 + tx * 8 + j;
            Out[(long)m * N + n] = acc[i][j] + bias[n];
        }
    }
}

// ---------------------------------------------------------------------------
extern "C" void kernel_launch(void* const* d_in, const int* in_sizes, int n_in,
                              void* d_out, int out_size)
{
    const float* x     = (const float*)d_in[0];
    const float* w_qkv = (const float*)d_in[1];
    const float* b_qkv = (const float*)d_in[2];
    const float* w_out = (const float*)d_in[3];
    const float* b_out = (const float*)d_in[4];
    float* out = (float*)d_out;

    // Stage 1: QKV projection + head scatter (BK=16, double-buffered)
    qkv_gemm<<<dim3(3 * HID / 128, (BATCH * SEQ) / 128), 256>>>(x, w_qkv, b_qkv);

    // Stage 2: causal flash attention (R14-exact)
    const int shmem = (64 * 132 + 2 * 64 * 68 + 128 * 68) * (int)sizeof(float);
    cudaFuncSetAttribute(flash_attn,
                         cudaFuncAttributeMaxDynamicSharedMemorySize, shmem);
    flash_attn<<<dim3(SEQ / 128, NHEAD, BATCH), 256, shmem>>>();

    // Stage 3: output projection (BK=16, double-buffered)
    out_gemm<<<dim3(HID / 128, (BATCH * SEQ) / 128), 256>>>(w_out, b_out, out);
}

// round 16
// speedup vs baseline: 1.0299x; 1.0299x over previous
#include <cuda_runtime.h>

#define BATCH 4
#define SEQ   2048
#define HID   1024
#define NHEAD 16
#define HDIM  64

// Scratch (static device globals — allowed; no runtime allocation)
__device__ float g_q[BATCH*NHEAD*SEQ*HDIM];
__device__ float g_k[BATCH*NHEAD*SEQ*HDIM];
__device__ float g_v[BATCH*NHEAD*SEQ*HDIM];
__device__ float g_attn[BATCH*SEQ*HID];

// ---------------------------------------------------------------------------
// Stage 1: QKV GEMM, BK=16, single-buffer register-staged prefetch
// (byte-identical to the R13/R14 passing version).
// ---------------------------------------------------------------------------
__global__ __launch_bounds__(256) void qkv_gemm(const float* __restrict__ A,
                                                const float* __restrict__ W,
                                                const float* __restrict__ bias)
{
    const int K = HID;
    const int N = 3 * HID;
    __shared__ float As[16][128];
    __shared__ float Bs[16][128];

    const int tid = threadIdx.x;
    const int m0 = blockIdx.y * 128;
    const int n0 = blockIdx.x * 128;

    const int arow  = tid >> 1;          // 0..127
    const int acolb = (tid & 1) * 8;     // 0 or 8
    const int brow  = tid >> 5;          // 0..7 (also handles brow+8)
    const int bcol  = (tid & 31) * 4;    // 0..124

    const float* Ap = A + (m0 + arow) * K + acolb;
    const float* Bp = W + brow * N + n0 + bcol;

    float acc[8][8] = {};
    const int ty = tid >> 4, tx = tid & 15;

    // stage tile 0
    float4 av0 = *(const float4*)(Ap);
    float4 av1 = *(const float4*)(Ap + 4);
    float4 bv0 = *(const float4*)(Bp);
    float4 bv1 = *(const float4*)(Bp + (long)8 * N);

    for (int k0 = 0; k0 < K; k0 += 16) {
        As[acolb + 0][arow] = av0.x;
        As[acolb + 1][arow] = av0.y;
        As[acolb + 2][arow] = av0.z;
        As[acolb + 3][arow] = av0.w;
        As[acolb + 4][arow] = av1.x;
        As[acolb + 5][arow] = av1.y;
        As[acolb + 6][arow] = av1.z;
        As[acolb + 7][arow] = av1.w;
        *(float4*)&Bs[brow    ][bcol] = bv0;
        *(float4*)&Bs[brow + 8][bcol] = bv1;
        __syncthreads();

        if (k0 + 16 < K) {
            av0 = *(const float4*)(Ap + k0 + 16);
            av1 = *(const float4*)(Ap + k0 + 20);
            bv0 = *(const float4*)(Bp + (long)(k0 + 16) * N);
            bv1 = *(const float4*)(Bp + (long)(k0 + 24) * N);
        }

        #pragma unroll
        for (int kk = 0; kk < 16; kk++) {
            float4 a0 = *(const float4*)&As[kk][ty * 8];
            float4 a1 = *(const float4*)&As[kk][ty * 8 + 4];
            float4 b0 = *(const float4*)&Bs[kk][tx * 8];
            float4 b1 = *(const float4*)&Bs[kk][tx * 8 + 4];
            float a[8] = {a0.x,a0.y,a0.z,a0.w,a1.x,a1.y,a1.z,a1.w};
            float b[8] = {b0.x,b0.y,b0.z,b0.w,b1.x,b1.y,b1.z,b1.w};
            #pragma unroll
            for (int i = 0; i < 8; i++)
                #pragma unroll
                for (int j = 0; j < 8; j++)
                    acc[i][j] += a[i] * b[j];
        }
        __syncthreads();
    }

    #pragma unroll
    for (int i = 0; i < 8; i++) {
        const int m = m0 + ty * 8 + i;
        const int bb = m >> 11;          // / SEQ
        const int s  = m & 2047;
        #pragma unroll
        for (int j = 0; j < 8; j++) {
            const int n = n0 + tx * 8 + j;
            const float v = acc[i][j] + bias[n];
            const int which = n >> 10;
            const int rem = n & 1023;
            const int h = rem >> 6;
            const int d = rem & 63;
            const int idx = (((bb * NHEAD) + h) * SEQ + s) * HDIM + d;
            if (which == 0)      g_q[idx] = v;
            else if (which == 1) g_k[idx] = v;
            else                 g_v[idx] = v;
        }
    }
}

// ---------------------------------------------------------------------------
// Stage 2: causal flash attention — R14-identical inner code; ONLY change:
// heavy q-tiles launch FIRST (qt reversed vs blockIdx.x) so the causal
// workload imbalance back-fills instead of forming an all-heavy last wave.
// smem: 64*132 + 2*64*68 + 128*68 floats = 103424 B.
// ---------------------------------------------------------------------------
__global__ __launch_bounds__(256, 2) void flash_attn()
{
    extern __shared__ float sm[];
    float (*QsT)[132] = (float(*)[132])sm;                          // [d][query]
    float (*KsT)[68]  = (float(*)[68])(sm + 64 * 132);              // [d][key]
    float (*Vs)[68]   = (float(*)[68])(sm + 64 * 132 + 64 * 68);    // [key][d]
    float (*Ps)[68]   = (float(*)[68])(sm + 64 * 132 + 2 * 64 * 68);// [query][key]

    const int b  = blockIdx.z;
    const int h  = blockIdx.y;
    const int qt = gridDim.x - 1 - blockIdx.x;   // heavy tiles first (LPT)
    const int q0 = qt * 128;

    const float* Qg  = g_q + (((long)(b * NHEAD + h)) * SEQ + q0) * HDIM;
    const float* Kg0 = g_k + ((long)(b * NHEAD + h)) * SEQ * HDIM;
    const float* Vg0 = g_v + ((long)(b * NHEAD + h)) * SEQ * HDIM;

    const int tid = threadIdx.x;
    const int ty = tid >> 4, tx = tid & 15;
    const int rbase = 8 * ty;

    // load Q tile transposed: QsT[d][q] = Q[q][d]  (128 rows x 64 d)
    for (int i = tid; i < 128 * 64; i += 256) {
        const int r = i >> 6, c = i & 63;
        QsT[c][r] = Qg[i];
    }

    float m_i[8], l_i[8], acc[8][4];
    #pragma unroll
    for (int i = 0; i < 8; i++) {
        m_i[i] = -1e30f;
        l_i[i] = 0.0f;
        #pragma unroll
        for (int j = 0; j < 4; j++) acc[i][j] = 0.0f;
    }

    const float scale = 0.125f; // HD^-0.5
    const int ntiles = 2 * qt + 2;

    for (int t = 0; t < ntiles; t++) {
        const int k0 = t * 64;
        __syncthreads();   // prior tile's K/V reads done (and Q load at t=0)
        for (int i = tid; i < 64 * 64; i += 256) {
            const int r = i >> 6, c = i & 63;
            KsT[c][r] = Kg0[k0 * HDIM + i];   // [d][key]
            Vs[r][c]  = Vg0[k0 * HDIM + i];   // [key][d]
        }
        __syncthreads();

        // S = Q K^T fused over all 8 rows: per d, 2 q-float4 + 1 k-float4
        float s[8][4];
        #pragma unroll
        for (int i = 0; i < 8; i++)
            #pragma unroll
            for (int j = 0; j < 4; j++) s[i][j] = 0.0f;

        #pragma unroll 4
        for (int d = 0; d < 64; d++) {
            const float4 qa = *(const float4*)&QsT[d][rbase];
            const float4 qb = *(const float4*)&QsT[d][rbase + 4];
            const float4 k4 = *(const float4*)&KsT[d][4 * tx];
            const float qv[8] = {qa.x, qa.y, qa.z, qa.w, qb.x, qb.y, qb.z, qb.w};
            const float kv[4] = {k4.x, k4.y, k4.z, k4.w};
            #pragma unroll
            for (int i = 0; i < 8; i++)
                #pragma unroll
                for (int j = 0; j < 4; j++)
                    s[i][j] += qv[i] * kv[j];
        }

        // mask + softmax + P write, per 4-row half (guards preserved)
        #pragma unroll
        for (int hf = 0; hf < 2; hf++) {
            const int rb = rbase + 4 * hf;
            const bool active = (q0 + rb + 3 >= k0);
            if (active) {
                #pragma unroll
                for (int i = 0; i < 4; i++) {
                    const int ii = 4 * hf + i;
                    const int rg = q0 + rb + i;
                    #pragma unroll
                    for (int j = 0; j < 4; j++) {
                        const int cg = k0 + 4 * tx + j;
                        float val = s[ii][j] * scale;
                        if (cg > rg) val = -1e30f;
                        s[ii][j] = val;
                    }
                }
                #pragma unroll
                for (int i = 0; i < 4; i++) {
                    const int ii = 4 * hf + i;
                    float mx = fmaxf(fmaxf(s[ii][0], s[ii][1]),
                                     fmaxf(s[ii][2], s[ii][3]));
                    #pragma unroll
                    for (int off = 8; off >= 1; off >>= 1)
                        mx = fmaxf(mx, __shfl_xor_sync(0xffffffffu, mx, off));
                    const float mn = fmaxf(m_i[ii], mx);
                    const float corr = __expf(m_i[ii] - mn);
                    m_i[ii] = mn;
                    float rs = 0.0f;
                    #pragma unroll
                    for (int j = 0; j < 4; j++) {
                        s[ii][j] = __expf(s[ii][j] - mn);
                        rs += s[ii][j];
                    }
                    #pragma unroll
                    for (int off = 8; off >= 1; off >>= 1)
                        rs += __shfl_xor_sync(0xffffffffu, rs, off);
                    l_i[ii] = l_i[ii] * corr + rs;
                    #pragma unroll
                    for (int j = 0; j < 4; j++) acc[ii][j] *= corr;
                }
                #pragma unroll
                for (int i = 0; i < 4; i++)
                    #pragma unroll
                    for (int j = 0; j < 4; j++)
                        Ps[rb + i][4 * tx + j] = s[4 * hf + i][j];
            } else {
                // fully masked half: P rows are exactly zero
                #pragma unroll
                for (int i = 0; i < 4; i++)
                    #pragma unroll
                    for (int j = 0; j < 4; j++)
                        Ps[rb + i][4 * tx + j] = 0.0f;
            }
        }
        __syncwarp();   // P rows exchanged only within the 16-lane tx group

        // O += P V : kk chunks of 4 (pv and vv both LDS.128)
        #pragma unroll 2
        for (int kk = 0; kk < 64; kk += 4) {
            float4 pv4[8];
            #pragma unroll
            for (int i = 0; i < 8; i++)
                pv4[i] = *(const float4*)&Ps[rbase + i][kk];
            float4 vv[4];
            #pragma unroll
            for (int c = 0; c < 4; c++)
                vv[c] = *(const float4*)&Vs[kk + c][4 * tx];
            #pragma unroll
            for (int i = 0; i < 8; i++) {
                const float pv[4] = {pv4[i].x, pv4[i].y, pv4[i].z, pv4[i].w};
                #pragma unroll
                for (int c = 0; c < 4; c++) {   // kk-sequential: same order as before
                    acc[i][0] += pv[c] * vv[c].x;
                    acc[i][1] += pv[c] * vv[c].y;
                    acc[i][2] += pv[c] * vv[c].z;
                    acc[i][3] += pv[c] * vv[c].w;
                }
            }
        }
        __syncwarp();   // own P rows fully consumed before next overwrite
    }

    // write out: g_attn[b][s][h*HD + d]
    #pragma unroll
    for (int i = 0; i < 8; i++) {
        const int rg = q0 + rbase + i;
        const float inv_l = 1.0f / l_i[i];
        #pragma unroll
        for (int j = 0; j < 4; j++) {
            g_attn[((long)(b * SEQ + rg)) * HID + h * HDIM + 4 * tx + j] =
                acc[i][j] * inv_l;
        }
    }
}

// ---------------------------------------------------------------------------
// Stage 3: output projection, BK=16, single-buffer (R13/R14-identical).
// ---------------------------------------------------------------------------
__global__ __launch_bounds__(256) void out_gemm(const float* __restrict__ W,
                                                const float* __restrict__ bias,
                                                float* __restrict__ Out)
{
    const int K = HID;
    const int N = HID;
    __shared__ float As[16][128];
    __shared__ float Bs[16][128];

    const int tid = threadIdx.x;
    const int m0 = blockIdx.y * 128;
    const int n0 = blockIdx.x * 128;

    const int arow  = tid >> 1;
    const int acolb = (tid & 1) * 8;
    const int brow  = tid >> 5;
    const int bcol  = (tid & 31) * 4;

    const float* Ap = g_attn + (long)(m0 + arow) * K + acolb;
    const float* Bp = W + brow * N + n0 + bcol;

    float acc[8][8] = {};
    const int ty = tid >> 4, tx = tid & 15;

    float4 av0 = *(const float4*)(Ap);
    float4 av1 = *(const float4*)(Ap + 4);
    float4 bv0 = *(const float4*)(Bp);
    float4 bv1 = *(const float4*)(Bp + (long)8 * N);

    for (int k0 = 0; k0 < K; k0 += 16) {
        As[acolb + 0][arow] = av0.x;
        As[acolb + 1][arow] = av0.y;
        As[acolb + 2][arow] = av0.z;
        As[acolb + 3][arow] = av0.w;
        As[acolb + 4][arow] = av1.x;
        As[acolb + 5][arow] = av1.y;
        As[acolb + 6][arow] = av1.z;
        As[acolb + 7][arow] = av1.w;
        *(float4*)&Bs[brow    ][bcol] = bv0;
        *(float4*)&Bs[brow + 8][bcol] = bv1;
        __syncthreads();

        if (k0 + 16 < K) {
            av0 = *(const float4*)(Ap + k0 + 16);
            av1 = *(const float4*)(Ap + k0 + 20);
            bv0 = *(const float4*)(Bp + (long)(k0 + 16) * N);
            bv1 = *(const float4*)(Bp + (long)(k0 + 24) * N);
        }

        #pragma unroll
        for (int kk = 0; kk < 16; kk++) {
            float4 a0 = *(const float4*)&As[kk][ty * 8];
            float4 a1 = *(const float4*)&As[kk][ty * 8 + 4];
            float4 b0 = *(const float4*)&Bs[kk][tx * 8];
            float4 b1 = *(const float4*)&Bs[kk][tx * 8 + 4];
            float a[8] = {a0.x,a0.y,a0.z,a0.w,a1.x,a1.y,a1.z,a1.w};
            float b[8] = {b0.x,b0.y,b0.z,b0.w,b1.x,b1.y,b1.z,b1.w};
            #pragma unroll
            for (int i = 0; i < 8; i++)
                #pragma unroll
                for (int j = 0; j < 8; j++)
                    acc[i][j] += a[i] * b[j];
        }
        __syncthreads();
    }

    #pragma unroll
    for (int i = 0; i < 8; i++) {
        const int m = m0 + ty * 8 + i;
        #pragma unroll
        for (int j = 0; j < 8; j++) {
            const int n = n0 + tx * 8 + j;
            Out[(long)m * N + n] = acc[i][j] + bias[n];
        }
    }
}

// ---------------------------------------------------------------------------
extern "C" void kernel_launch(void* const* d_in, const int* in_sizes, int n_in,
                              void* d_out, int out_size)
{
    const float* x     = (const float*)d_in[0];
    const float* w_qkv = (const float*)d_in[1];
    const float* b_qkv = (const float*)d_in[2];
    const float* w_out = (const float*)d_in[3];
    const float* b_out = (const float*)d_in[4];
    float* out = (float*)d_out;

    // Stage 1: QKV projection + head scatter (BK=16, single-buffer)
    qkv_gemm<<<dim3(3 * HID / 128, (BATCH * SEQ) / 128), 256>>>(x, w_qkv, b_qkv);

    // Stage 2: causal flash attention (heavy tiles first)
    const int shmem = (64 * 132 + 2 * 64 * 68 + 128 * 68) * (int)sizeof(float);
    cudaFuncSetAttribute(flash_attn,
                         cudaFuncAttributeMaxDynamicSharedMemorySize, shmem);
    flash_attn<<<dim3(SEQ / 128, NHEAD, BATCH), 256, shmem>>>();

    // Stage 3: output projection (BK=16, single-buffer)
    out_gemm<<<dim3(HID / 128, (BATCH * SEQ) / 128), 256>>>(w_out, b_out, out);
}